// round 10
// baseline (speedup 1.0000x reference)
#include <cuda_runtime.h>
#include <cuda_bf16.h>
#include <cooperative_groups.h>
#include <math.h>
#include <stdint.h>

namespace cg = cooperative_groups;

#define T_STEPS 100
#define BATCH   256
#define IN_DIM  784
#define HID     1024
#define OUTD    10
#define P_DIM   64
#define ALPHA   0.05f   // DT / TAUM

#define M_TOT   (T_STEPS * BATCH)   // 25600
#define K_PAD   896                 // 7 * 128 (s8 bytes per row)
#define N_CHUNK 7
#define TILES_PER_T 32              // 2 m-tiles * 16 n-tiles per timestep

#define NCTAS_LOOP 64               // 16 clusters x 4 (16 batch rows each)
#define NCTAS_GEMM 3200             // 200 m-tiles x 16 n-tiles (128m x 64n)
#define NCTAS_ALL  (NCTAS_LOOP + NCTAS_GEMM)

// ---------------- scratch (static device globals) ----------------
__device__ float  g_Iin[(size_t)T_STEPS * BATCH * HID];
__device__ float  g_rm [BATCH * HID];
__device__ int8_t g_spk8[(size_t)M_TOT * K_PAD];
__device__ int8_t g_Wq1 [(size_t)HID * K_PAD];
__device__ int8_t g_Wq2 [(size_t)HID * K_PAD];
__device__ unsigned int g_tdone[T_STEPS];

// ---------------- helpers ----------------
__device__ __forceinline__ uint32_t smem_u32(const void* p) {
    uint32_t a;
    asm("{ .reg .u64 t; cvta.to.shared.u64 t, %1; cvt.u32.u64 %0, t; }" : "=r"(a) : "l"(p));
    return a;
}
#define SWZ128(o) ((o) ^ (((o) >> 3) & 0x70))
#define CP_COMMIT() asm volatile("cp.async.commit_group;" ::: "memory")
#define CP_WAIT(n)  asm volatile("cp.async.wait_group %0;" :: "n"(n) : "memory")

__device__ __forceinline__ void ldm_x4(uint32_t* r, uint32_t addr) {
    asm volatile("ldmatrix.sync.aligned.m8n8.x4.shared.b16 {%0,%1,%2,%3}, [%4];"
                 : "=r"(r[0]), "=r"(r[1]), "=r"(r[2]), "=r"(r[3]) : "r"(addr));
}
__device__ __forceinline__ void mma_bf16(float* c, const uint32_t* a, uint32_t b0, uint32_t b1) {
    asm volatile("mma.sync.aligned.m16n8k16.row.col.f32.bf16.bf16.f32 "
                 "{%0,%1,%2,%3}, {%4,%5,%6,%7}, {%8,%9}, {%0,%1,%2,%3};"
                 : "+f"(c[0]), "+f"(c[1]), "+f"(c[2]), "+f"(c[3])
                 : "r"(a[0]), "r"(a[1]), "r"(a[2]), "r"(a[3]), "r"(b0), "r"(b1));
}
__device__ __forceinline__ void mma_s8(int* c, const uint32_t* a, uint32_t b0, uint32_t b1) {
    asm volatile("mma.sync.aligned.m16n8k32.row.col.s32.s8.s8.s32 "
                 "{%0,%1,%2,%3}, {%4,%5,%6,%7}, {%8,%9}, {%0,%1,%2,%3};"
                 : "+r"(c[0]), "+r"(c[1]), "+r"(c[2]), "+r"(c[3])
                 : "r"(a[0]), "r"(a[1]), "r"(a[2]), "r"(a[3]), "r"(b0), "r"(b1));
}

// ---------------- prep kernels (vectorized, int8) ----------------
// spk -> s8 {0,1}, K-padded to 896.  16 cols per thread.
__global__ void prep_spk_kernel(const float* __restrict__ spk) {
    int i = blockIdx.x * blockDim.x + threadIdx.x;
    if (i >= M_TOT * (K_PAD / 16)) return;
    int row = i / (K_PAD / 16);
    int c0  = (i % (K_PAD / 16)) * 16;
    int8_t v[16];
    if (c0 <= IN_DIM - 16) {
        const float4* src = (const float4*)&spk[(size_t)row * IN_DIM + c0];
        #pragma unroll
        for (int q = 0; q < 4; q++) {
            float4 f = src[q];
            v[q * 4 + 0] = (int8_t)__float2int_rn(f.x);
            v[q * 4 + 1] = (int8_t)__float2int_rn(f.y);
            v[q * 4 + 2] = (int8_t)__float2int_rn(f.z);
            v[q * 4 + 3] = (int8_t)__float2int_rn(f.w);
        }
    } else {
        #pragma unroll
        for (int q = 0; q < 16; q++) v[q] = 0;
    }
    *(uint4*)&g_spk8[(size_t)row * K_PAD + c0] = *(uint4*)v;
}

// Win -> (q1, q2): Win ~= (128*q1 + q2) / 65536, fixed power-of-2 scales.
__global__ void prep_win_kernel(const float* __restrict__ Win) {
    int i = blockIdx.x * blockDim.x + threadIdx.x;
    if (blockIdx.x == 0 && threadIdx.x < T_STEPS) g_tdone[threadIdx.x] = 0u;
    if (i >= HID * (K_PAD / 16)) return;
    int row = i / (K_PAD / 16);
    int c0  = (i % (K_PAD / 16)) * 16;
    int8_t v1[16], v2[16];
    if (c0 <= IN_DIM - 16) {
        const float4* src = (const float4*)&Win[(size_t)row * IN_DIM + c0];
        #pragma unroll
        for (int q = 0; q < 4; q++) {
            float4 f = src[q];
            float fv[4] = {f.x, f.y, f.z, f.w};
            #pragma unroll
            for (int j = 0; j < 4; j++) {
                int q1 = __float2int_rn(fv[j] * 512.0f);
                q1 = max(-127, min(127, q1));
                int q2 = __float2int_rn(fv[j] * 65536.0f - (float)(q1 * 128));
                q2 = max(-127, min(127, q2));
                v1[q * 4 + j] = (int8_t)q1;
                v2[q * 4 + j] = (int8_t)q2;
            }
        }
    } else {
        #pragma unroll
        for (int q = 0; q < 16; q++) { v1[q] = 0; v2[q] = 0; }
    }
    *(uint4*)&g_Wq1[(size_t)row * K_PAD + c0] = *(uint4*)v1;
    *(uint4*)&g_Wq2[(size_t)row * K_PAD + c0] = *(uint4*)v2;
}

// ---------------- IMMA gemm role: Iin = spk8 @ (128*q1 + q2)^T / 65536 ----------------
// CTA tile 128m x 64n; K chunks of 128 s8 (128B SW128 rows); 2-stage cp.async.
// 8 warps as 4(m) x 2(n); warp tile 32m x 32n; s32 accumulators (exact).
#define A_TILE_B  16384              // 128 rows * 128 B
#define B_TILE_B  8192               // 64 rows * 128 B
#define STAGE_B   (A_TILE_B + 2 * B_TILE_B)   // 32768
#define GEMM_SMEM (2 * STAGE_B)               // 65536

__device__ __forceinline__ void copy_rows(uint32_t sdst, const int8_t* __restrict__ g,
                                          int row0, int kb0, int nrows, int tid) {
    const int units = nrows * 8;     // 16B units
    for (int i = tid; i < units; i += 256) {
        int row = i >> 3;
        int cb  = i & 7;
        const void* gp = g + (size_t)(row0 + row) * K_PAD + kb0 + cb * 16;
        uint32_t so = sdst + SWZ128(row * 128 + cb * 16);
        asm volatile("cp.async.cg.shared.global [%0], [%1], 16;" :: "r"(so), "l"(gp));
    }
}

__device__ void gemm_role(char* smraw, int gid) {
    const uint32_t sb  = smem_u32(smraw);
    const int tid  = threadIdx.x;
    const int wid  = tid >> 5;
    const int lane = tid & 31;
    const int m0 = (gid >> 4) * 128;      // m-tile ascending == timestep ascending
    const int n0 = (gid & 15) * 64;
    const int wm = (wid & 3) * 32;        // warp m offset
    const int wn = (wid >> 2) * 32;       // warp n offset

    const uint32_t stA[2]  = {sb,              sb + STAGE_B};
    const uint32_t stB1[2] = {sb + A_TILE_B,   sb + STAGE_B + A_TILE_B};
    const uint32_t stB2[2] = {stB1[0] + B_TILE_B, stB1[1] + B_TILE_B};

    int acc1[2][4][4], acc2[2][4][4];
    #pragma unroll
    for (int mi = 0; mi < 2; mi++)
        #pragma unroll
        for (int nj = 0; nj < 4; nj++)
            #pragma unroll
            for (int q = 0; q < 4; q++) { acc1[mi][nj][q] = 0; acc2[mi][nj][q] = 0; }

    copy_rows(stA[0], g_spk8, m0, 0, 128, tid);
    copy_rows(stB1[0], g_Wq1, n0, 0, 64, tid);
    copy_rows(stB2[0], g_Wq2, n0, 0, 64, tid);
    CP_COMMIT();
    copy_rows(stA[1], g_spk8, m0, 128, 128, tid);
    copy_rows(stB1[1], g_Wq1, n0, 128, 64, tid);
    copy_rows(stB2[1], g_Wq2, n0, 128, 64, tid);
    CP_COMMIT();

    const int arow  = wm + (lane & 15);
    const int acolL = (lane >> 4) << 4;
    const int brow  = (lane & 7) + ((lane >> 4) << 3);
    const int bcolL = ((lane >> 3) & 1) << 4;

    for (int k = 0; k < N_CHUNK; k++) {
        const int s = k & 1;
        if (k < N_CHUNK - 1) CP_WAIT(1); else CP_WAIT(0);
        __syncthreads();

        #pragma unroll
        for (int ks = 0; ks < 4; ks++) {
            const int kb = ks * 32;           // byte offset of this k32 within 128B row
            uint32_t af[2][4];
            ldm_x4(af[0], stA[s] + SWZ128((arow)      * 128 + kb + acolL));
            ldm_x4(af[1], stA[s] + SWZ128((arow + 16) * 128 + kb + acolL));

            #pragma unroll
            for (int nb = 0; nb < 2; nb++) {
                const uint32_t boff = SWZ128((wn + nb * 16 + brow) * 128 + kb + bcolL);
                uint32_t b1[4], b2[4];
                ldm_x4(b1, stB1[s] + boff);
                ldm_x4(b2, stB2[s] + boff);
                #pragma unroll
                for (int mi = 0; mi < 2; mi++) {
                    mma_s8(acc1[mi][nb * 2 + 0], af[mi], b1[0], b1[1]);
                    mma_s8(acc1[mi][nb * 2 + 1], af[mi], b1[2], b1[3]);
                    mma_s8(acc2[mi][nb * 2 + 0], af[mi], b2[0], b2[1]);
                    mma_s8(acc2[mi][nb * 2 + 1], af[mi], b2[2], b2[3]);
                }
            }
        }
        __syncthreads();

        if (k + 2 < N_CHUNK) {
            const int kb0 = (k + 2) * 128;
            copy_rows(stA[s], g_spk8, m0, kb0, 128, tid);
            copy_rows(stB1[s], g_Wq1, n0, kb0, 64, tid);
            copy_rows(stB2[s], g_Wq2, n0, kb0, 64, tid);
            CP_COMMIT();
        }
    }

    // epilogue: I = (128*acc1 + acc2) / 65536
    const float INV64K = 1.0f / 65536.0f;
    const int r0 = lane >> 2;
    const int c0 = (lane & 3) * 2;
    #pragma unroll
    for (int mi = 0; mi < 2; mi++) {
        #pragma unroll
        for (int nj = 0; nj < 4; nj++) {
            const int row = m0 + wm + mi * 16 + r0;
            const int col = n0 + wn + nj * 8 + c0;
            float* base = &g_Iin[(size_t)row * HID + col];
            float v0 = (float)(acc1[mi][nj][0] * 128 + acc2[mi][nj][0]) * INV64K;
            float v1 = (float)(acc1[mi][nj][1] * 128 + acc2[mi][nj][1]) * INV64K;
            float v2 = (float)(acc1[mi][nj][2] * 128 + acc2[mi][nj][2]) * INV64K;
            float v3 = (float)(acc1[mi][nj][3] * 128 + acc2[mi][nj][3]) * INV64K;
            *(float2*)base             = make_float2(v0, v1);
            *(float2*)(base + 8 * HID) = make_float2(v2, v3);
        }
    }

    __syncthreads();
    if (tid == 0) {
        __threadfence();
        atomicAdd(&g_tdone[gid >> 5], 1u);
    }
}

// ---------------- loop role: unchanged from R9 (16 rows / cluster, bf16 HMMA) ----------------
#define CLUSTER_N   4
#define ROWS_PER_CL 16
#define H_PER_CTA   256

#define L_OFF_POUT  0
#define L_OFF_WPL   32768
#define L_OFF_TH    65536
#define L_OFF_U     73728
#define L_OFF_UPART 75776
#define L_OFF_MBOX  83968
#define LOOP_SMEM   100352

#define FUSED_SMEM  (LOOP_SMEM > GEMM_SMEM ? LOOP_SMEM : GEMM_SMEM)

__device__ void loop_role(char* smraw, int bid,
                          const float* __restrict__ pin, const float* __restrict__ pout,
                          const float* __restrict__ l) {
    const uint32_t sb = smem_u32(smraw);

    cg::cluster_group cl = cg::this_cluster();
    const int rank = cl.block_rank();
    const int cidx = bid / CLUSTER_N;
    const int b0   = cidx * ROWS_PER_CL;
    const int H0   = rank * H_PER_CTA;
    const int tid  = threadIdx.x;
    const int wid  = tid >> 5;
    const int lane = tid & 31;

    for (int i = tid; i < H_PER_CTA * P_DIM; i += 256) {
        int hl = i >> 6;
        int p  = i & 63;
        float pv = pout[(size_t)(H0 + hl) * P_DIM + p];
        *(__nv_bfloat16*)(smraw + L_OFF_POUT + (hl >> 6) * 8192
                          + SWZ128(p * 128 + (hl & 63) * 2)) = __float2bfloat16(pv);
        float wv = pin[(size_t)(H0 + hl) * P_DIM + p] * l[p];
        *(__nv_bfloat16*)(smraw + L_OFF_WPL + SWZ128(hl * 128 + p * 2)) = __float2bfloat16(wv);
    }
    for (int i = tid; i < (8192 + 2048) / 4; i += 256)
        ((uint32_t*)(smraw + L_OFF_TH))[i] = 0;

    const int kg   = wid >> 2;
    const int wn16 = (wid & 3) * 16;
    const int aRow = lane & 15;
    const int aCol = (lane >> 4) << 4;
    const int bRow = (lane & 7) + ((lane >> 4) << 3);
    const int bCol = ((lane >> 3) & 1) << 4;
    const int r    = lane >> 2;
    const int c2   = (lane & 3) * 2;

    const int r_e  = tid >> 4;
    const int pe   = (tid & 15) * 4;
    char* mboxLocal = smraw + L_OFF_MBOX;
    char* peerMb[CLUSTER_N];
    #pragma unroll
    for (int rk = 0; rk < CLUSTER_N; rk++)
        peerMb[rk] = (char*)cl.map_shared_rank((void*)mboxLocal, rk);

    float2 memv[8], rmv[8];
    #pragma unroll
    for (int j = 0; j < 8; j++) { memv[j] = make_float2(0.f, 0.f); rmv[j] = make_float2(-2.f, -2.f); }

    cl.sync();

    for (int t = 0; t < T_STEPS; t++) {
        if (tid == 0) {
            volatile unsigned int* f = &g_tdone[t];
            while (*f < TILES_PER_T) {}
            __threadfence();
        }
        __syncthreads();
        const int buf = t & 1;

        float2 iin[8];
        {
            const size_t base = ((size_t)t * BATCH + b0 + r) * HID + H0 + wid * 32 + c2;
            #pragma unroll
            for (int nb = 0; nb < 2; nb++)
                #pragma unroll
                for (int sub = 0; sub < 2; sub++) {
                    iin[nb * 2 + sub]     = __ldcs((const float2*)&g_Iin[base + nb * 16 + sub * 8]);
                    iin[4 + nb * 2 + sub] = __ldcs((const float2*)&g_Iin[base + 8 * HID + nb * 16 + sub * 8]);
                }
        }

        float accA[2][4] = {{0.f,0.f,0.f,0.f},{0.f,0.f,0.f,0.f}};
        #pragma unroll
        for (int cc = 0; cc < 2; cc++) {
            const int ch = kg * 2 + cc;
            const uint32_t thB = sb + L_OFF_TH + ch * 2048;
            const uint32_t poB = sb + L_OFF_POUT + ch * 8192;
            #pragma unroll
            for (int ks = 0; ks < 4; ks++) {
                const int kb = ks * 32;
                uint32_t af[4], bf[4];
                ldm_x4(af, thB + SWZ128(aRow * 128 + kb + aCol));
                ldm_x4(bf, poB + SWZ128((wn16 + bRow) * 128 + kb + bCol));
                mma_bf16(accA[0], af, bf[0], bf[1]);
                mma_bf16(accA[1], af, bf[2], bf[3]);
            }
        }
        {
            float* up = (float*)(smraw + L_OFF_UPART);
            const int rowA = (kg * 16 + r) * 64 + wn16;
            const int rowB = (kg * 16 + r + 8) * 64 + wn16;
            *(float2*)&up[rowA + 0 + c2] = make_float2(accA[0][0], accA[0][1]);
            *(float2*)&up[rowA + 8 + c2] = make_float2(accA[1][0], accA[1][1]);
            *(float2*)&up[rowB + 0 + c2] = make_float2(accA[0][2], accA[0][3]);
            *(float2*)&up[rowB + 8 + c2] = make_float2(accA[1][2], accA[1][3]);
        }
        __syncthreads();

        {
            const float* up = (const float*)(smraw + L_OFF_UPART);
            float v0 = up[r_e * 64 + pe + 0] + up[(16 + r_e) * 64 + pe + 0];
            float v1 = up[r_e * 64 + pe + 1] + up[(16 + r_e) * 64 + pe + 1];
            float v2 = up[r_e * 64 + pe + 2] + up[(16 + r_e) * 64 + pe + 2];
            float v3 = up[r_e * 64 + pe + 3] + up[(16 + r_e) * 64 + pe + 3];
            uint2 pk;
            __nv_bfloat162 b01 = __floats2bfloat162_rn(v0, v1);
            __nv_bfloat162 b23 = __floats2bfloat162_rn(v2, v3);
            pk.x = *(uint32_t*)&b01;
            pk.y = *(uint32_t*)&b23;
            const int moff = ((buf * CLUSTER_N + rank) * 16 + r_e) * 128 + pe * 2;
            #pragma unroll
            for (int rk = 0; rk < CLUSTER_N; rk++)
                *(uint2*)(peerMb[rk] + moff) = pk;
        }
        cl.sync();

        {
            float s0 = 0.f, s1 = 0.f, s2 = 0.f, s3 = 0.f;
            #pragma unroll
            for (int rk = 0; rk < CLUSTER_N; rk++) {
                uint2 q = *(uint2*)(mboxLocal + ((buf * CLUSTER_N + rk) * 16 + r_e) * 128 + pe * 2);
                float2 f01 = __bfloat1622float2(*(__nv_bfloat162*)&q.x);
                float2 f23 = __bfloat1622float2(*(__nv_bfloat162*)&q.y);
                s0 += f01.x; s1 += f01.y; s2 += f23.x; s3 += f23.y;
            }
            uint2 pk;
            __nv_bfloat162 b01 = __floats2bfloat162_rn(s0, s1);
            __nv_bfloat162 b23 = __floats2bfloat162_rn(s2, s3);
            pk.x = *(uint32_t*)&b01;
            pk.y = *(uint32_t*)&b23;
            *(uint2*)(smraw + L_OFF_U + SWZ128(r_e * 128 + pe * 2)) = pk;
        }
        __syncthreads();

        float accB[2][2][4];
        #pragma unroll
        for (int nb = 0; nb < 2; nb++)
            #pragma unroll
            for (int sub = 0; sub < 2; sub++)
                #pragma unroll
                for (int q = 0; q < 4; q++) accB[nb][sub][q] = 0.f;

        const uint32_t uB = sb + L_OFF_U;
        const uint32_t wB = sb + L_OFF_WPL;
        #pragma unroll
        for (int ks = 0; ks < 4; ks++) {
            const int kb = ks * 32;
            uint32_t af[4];
            ldm_x4(af, uB + SWZ128(aRow * 128 + kb + aCol));
            #pragma unroll
            for (int nb = 0; nb < 2; nb++) {
                uint32_t bf[4];
                ldm_x4(bf, wB + SWZ128((wid * 32 + nb * 16 + bRow) * 128 + kb + bCol));
                mma_bf16(accB[nb][0], af, bf[0], bf[1]);
                mma_bf16(accB[nb][1], af, bf[2], bf[3]);
            }
        }

        #pragma unroll
        for (int nb = 0; nb < 2; nb++) {
            #pragma unroll
            for (int sub = 0; sub < 2; sub++) {
                const int j  = nb * 2 + sub;
                const int hc = wid * 32 + nb * 16 + sub * 8 + c2;
                const uint32_t thBase = (uint32_t)(L_OFF_TH + (hc >> 6) * 2048);
                {
                    float m0 = (iin[j].x + accB[nb][sub][0] - memv[j].x) * ALPHA;
                    float m1 = (iin[j].y + accB[nb][sub][1] - memv[j].y) * ALPHA;
                    memv[j].x = m0;  memv[j].y = m1;
                    float tv0 = tanhf(m0), tv1 = tanhf(m1);
                    rmv[j].x = fmaxf(rmv[j].x, tv0);
                    rmv[j].y = fmaxf(rmv[j].y, tv1);
                    *(__nv_bfloat162*)(smraw + thBase + SWZ128(r * 128 + (hc & 63) * 2)) =
                        __floats2bfloat162_rn(tv0, tv1);
                }
                {
                    float m0 = (iin[4 + j].x + accB[nb][sub][2] - memv[4 + j].x) * ALPHA;
                    float m1 = (iin[4 + j].y + accB[nb][sub][3] - memv[4 + j].y) * ALPHA;
                    memv[4 + j].x = m0;  memv[4 + j].y = m1;
                    float tv0 = tanhf(m0), tv1 = tanhf(m1);
                    rmv[4 + j].x = fmaxf(rmv[4 + j].x, tv0);
                    rmv[4 + j].y = fmaxf(rmv[4 + j].y, tv1);
                    *(__nv_bfloat162*)(smraw + thBase + SWZ128((r + 8) * 128 + (hc & 63) * 2)) =
                        __floats2bfloat162_rn(tv0, tv1);
                }
            }
        }
    }

    #pragma unroll
    for (int nb = 0; nb < 2; nb++)
        #pragma unroll
        for (int sub = 0; sub < 2; sub++) {
            const int j  = nb * 2 + sub;
            const int hc = wid * 32 + nb * 16 + sub * 8 + c2;
            *(float2*)&g_rm[(size_t)(b0 + r) * HID + H0 + hc]     = rmv[j];
            *(float2*)&g_rm[(size_t)(b0 + 8 + r) * HID + H0 + hc] = rmv[4 + j];
        }
}

// ---------------- fused heterogeneous kernel ----------------
__global__ void __cluster_dims__(CLUSTER_N, 1, 1) __launch_bounds__(256, 2)
fused_kernel(const float* __restrict__ pin, const float* __restrict__ pout,
             const float* __restrict__ l) {
    extern __shared__ char smraw[];
    const int bid = blockIdx.x;
    if (bid < NCTAS_LOOP) {
        loop_role(smraw, bid, pin, pout, l);
    } else {
        gemm_role(smraw, bid - NCTAS_LOOP);
    }
}

// ---------------- readout ----------------
__global__ __launch_bounds__(128) void readout_kernel(const float* __restrict__ Wout,
                                                      float* __restrict__ out) {
    const int b    = blockIdx.x;
    const int tid  = threadIdx.x;
    const int lane = tid & 31;
    const int wid  = tid >> 5;
    __shared__ float red[4][OUTD];

    float pacc[OUTD];
    #pragma unroll
    for (int o = 0; o < OUTD; o++) pacc[o] = 0.0f;

    #pragma unroll
    for (int hh = 0; hh < HID / 128; hh++) {
        int h = tid + hh * 128;
        float rv = g_rm[(size_t)b * HID + h];
        #pragma unroll
        for (int o = 0; o < OUTD; o++) pacc[o] = fmaf(rv, Wout[o * HID + h], pacc[o]);
    }
    #pragma unroll
    for (int o = 0; o < OUTD; o++) {
        #pragma unroll
        for (int off = 16; off > 0; off >>= 1)
            pacc[o] += __shfl_down_sync(0xffffffffu, pacc[o], off);
    }
    if (lane == 0) {
        #pragma unroll
        for (int o = 0; o < OUTD; o++) red[wid][o] = pacc[o];
    }
    __syncthreads();
    if (tid == 0) {
        float v[OUTD];
        #pragma unroll
        for (int o = 0; o < OUTD; o++)
            v[o] = red[0][o] + red[1][o] + red[2][o] + red[3][o];
        float mx = v[0];
        #pragma unroll
        for (int o = 1; o < OUTD; o++) mx = fmaxf(mx, v[o]);
        float e[OUTD], sum = 0.0f;
        #pragma unroll
        for (int o = 0; o < OUTD; o++) { e[o] = expf(v[o] - mx); sum += e[o]; }
        float inv = 1.0f / sum;
        #pragma unroll
        for (int o = 0; o < OUTD; o++) out[b * OUTD + o] = e[o] * inv;
    }
}

// ---------------- launch ----------------
extern "C" void kernel_launch(void* const* d_in, const int* in_sizes, int n_in,
                              void* d_out, int out_size) {
    const float* spk  = (const float*)d_in[0];
    const float* Win  = (const float*)d_in[1];
    const float* Wout = (const float*)d_in[2];
    const float* pin  = (const float*)d_in[3];
    const float* pout = (const float*)d_in[4];
    const float* l    = (const float*)d_in[5];
    float* out = (float*)d_out;

    static bool init = false;
    if (!init) {
        cudaFuncSetAttribute(fused_kernel, cudaFuncAttributeMaxDynamicSharedMemorySize, FUSED_SMEM);
        init = true;
    }

    {
        int n = M_TOT * (K_PAD / 16);
        prep_spk_kernel<<<(n + 255) / 256, 256>>>(spk);
    }
    {
        int n = HID * (K_PAD / 16);
        prep_win_kernel<<<(n + 255) / 256, 256>>>(Win);
    }
    fused_kernel<<<NCTAS_ALL, 256, FUSED_SMEM>>>(pin, pout, l);
    readout_kernel<<<BATCH, 128>>>(Wout, out);
}

// round 11
// speedup vs baseline: 2.0123x; 2.0123x over previous
#include <cuda_runtime.h>
#include <cuda_bf16.h>
#include <cooperative_groups.h>
#include <math.h>
#include <stdint.h>

namespace cg = cooperative_groups;

#define T_STEPS 100
#define BATCH   256
#define IN_DIM  784
#define HID     1024
#define OUTD    10
#define P_DIM   64
#define ALPHA   0.05f   // DT / TAUM

#define M_TOT   (T_STEPS * BATCH)   // 25600
#define K_PAD   832                 // 13 * 64 bf16
#define N_CHUNK 13
#define TILES_PER_T 16

#define NPREP_SPK 100
#define NPREP_WIN 16
#define BID_PREP0 64
#define BID_WIN0  164
#define BID_GEMM0 180
#define NCTAS_LOOP 64
#define NCTAS_ALL  1780             // 64 loop + 100 prep + 16 win + 1600 gemm

// ---------------- scratch (static device globals) ----------------
__device__ float g_Iin[(size_t)T_STEPS * BATCH * HID];
__device__ float g_rm [BATCH * HID];
__device__ __nv_bfloat16 g_spkb [(size_t)M_TOT * K_PAD];
__device__ __nv_bfloat16 g_WinHi[(size_t)HID * K_PAD];
__device__ __nv_bfloat16 g_WinLo[(size_t)HID * K_PAD];
__device__ unsigned int g_tdone[T_STEPS];
__device__ unsigned int g_pdone[T_STEPS];
__device__ unsigned int g_wdone;

// ---------------- helpers ----------------
__device__ __forceinline__ uint32_t smem_u32(const void* p) {
    uint32_t a;
    asm("{ .reg .u64 t; cvta.to.shared.u64 t, %1; cvt.u32.u64 %0, t; }" : "=r"(a) : "l"(p));
    return a;
}
#define SWZ128(o) ((o) ^ (((o) >> 3) & 0x70))
#define CP_COMMIT() asm volatile("cp.async.commit_group;" ::: "memory")
#define CP_WAIT(n)  asm volatile("cp.async.wait_group %0;" :: "n"(n) : "memory")

__device__ __forceinline__ void ldm_x4(uint32_t* r, uint32_t addr) {
    asm volatile("ldmatrix.sync.aligned.m8n8.x4.shared.b16 {%0,%1,%2,%3}, [%4];"
                 : "=r"(r[0]), "=r"(r[1]), "=r"(r[2]), "=r"(r[3]) : "r"(addr));
}
__device__ __forceinline__ void mma_bf16(float* c, const uint32_t* a, uint32_t b0, uint32_t b1) {
    asm volatile("mma.sync.aligned.m16n8k16.row.col.f32.bf16.bf16.f32 "
                 "{%0,%1,%2,%3}, {%4,%5,%6,%7}, {%8,%9}, {%0,%1,%2,%3};"
                 : "+f"(c[0]), "+f"(c[1]), "+f"(c[2]), "+f"(c[3])
                 : "r"(a[0]), "r"(a[1]), "r"(a[2]), "r"(a[3]), "r"(b0), "r"(b1));
}

// ---------------- flag reset (serial, before fused launch; replay-safe) ----------------
__global__ void zero_flags_kernel() {
    int i = threadIdx.x;
    if (i < T_STEPS) { g_tdone[i] = 0u; g_pdone[i] = 0u; }
    if (i == 0) g_wdone = 0u;
}

// ---------------- prep roles (inside fused kernel) ----------------
__device__ void prep_spk_role(const float* __restrict__ spk, int ts) {
    const int tid  = threadIdx.x;
    const int row0 = ts * BATCH;
    for (int i = tid; i < BATCH * (K_PAD / 8); i += 256) {
        int row = i / (K_PAD / 8);
        int c0  = (i % (K_PAD / 8)) * 8;
        __nv_bfloat16 v[8];
        if (c0 < IN_DIM) {   // c0 multiple of 8, 784 = 98*8 -> full float4 pair valid
            const float4* src = (const float4*)&spk[(size_t)(row0 + row) * IN_DIM + c0];
            float4 f0 = src[0], f1 = src[1];
            v[0] = __float2bfloat16(f0.x); v[1] = __float2bfloat16(f0.y);
            v[2] = __float2bfloat16(f0.z); v[3] = __float2bfloat16(f0.w);
            v[4] = __float2bfloat16(f1.x); v[5] = __float2bfloat16(f1.y);
            v[6] = __float2bfloat16(f1.z); v[7] = __float2bfloat16(f1.w);
        } else {
            #pragma unroll
            for (int j = 0; j < 8; j++) v[j] = __float2bfloat16(0.0f);
        }
        *(uint4*)&g_spkb[(size_t)(row0 + row) * K_PAD + c0] = *(uint4*)v;
    }
    __syncthreads();
    if (tid == 0) {
        __threadfence();
        atomicExch(&g_pdone[ts], 1u);
    }
}

__device__ void prep_win_role(const float* __restrict__ Win, int w) {
    const int tid  = threadIdx.x;
    const int row0 = w * (HID / NPREP_WIN);   // 64 rows per CTA
    for (int i = tid; i < (HID / NPREP_WIN) * (K_PAD / 8); i += 256) {
        int row = i / (K_PAD / 8);
        int c0  = (i % (K_PAD / 8)) * 8;
        __nv_bfloat16 hi[8], lo[8];
        if (c0 < IN_DIM) {
            const float4* src = (const float4*)&Win[(size_t)(row0 + row) * IN_DIM + c0];
            float4 f0 = src[0], f1 = src[1];
            float fv[8] = {f0.x, f0.y, f0.z, f0.w, f1.x, f1.y, f1.z, f1.w};
            #pragma unroll
            for (int j = 0; j < 8; j++) {
                __nv_bfloat16 h = __float2bfloat16(fv[j]);
                hi[j] = h;
                lo[j] = __float2bfloat16(fv[j] - __bfloat162float(h));
            }
        } else {
            #pragma unroll
            for (int j = 0; j < 8; j++) { hi[j] = __float2bfloat16(0.0f); lo[j] = __float2bfloat16(0.0f); }
        }
        *(uint4*)&g_WinHi[(size_t)(row0 + row) * K_PAD + c0] = *(uint4*)hi;
        *(uint4*)&g_WinLo[(size_t)(row0 + row) * K_PAD + c0] = *(uint4*)lo;
    }
    __syncthreads();
    if (tid == 0) {
        __threadfence();
        atomicAdd(&g_wdone, 1u);
    }
}

// ---------------- gemm role (R9-verified bf16 HMMA, + prep spin) ----------------
#define TILE_BYTES  16384
#define STAGE_BYTES (3 * TILE_BYTES)
#define GEMM_SMEM   (2 * STAGE_BYTES)   // 98304

__device__ __forceinline__ void copy_tile(uint32_t sdst, const __nv_bfloat16* __restrict__ g,
                                          int row0, int k0, int tid) {
    #pragma unroll
    for (int j = 0; j < 4; j++) {
        int i   = tid + j * 256;
        int row = i >> 3;
        int cb  = i & 7;
        const void* gp = g + (size_t)(row0 + row) * K_PAD + k0 + cb * 8;
        uint32_t so = sdst + SWZ128(row * 128 + cb * 16);
        asm volatile("cp.async.cg.shared.global [%0], [%1], 16;" :: "r"(so), "l"(gp));
    }
}

__device__ void gemm_role(char* smraw, int gid) {
    const uint32_t sb  = smem_u32(smraw);
    const int tid  = threadIdx.x;
    const int wid  = tid >> 5;
    const int lane = tid & 31;
    const int m0 = (gid >> 3) * 128;     // m-tile ascending == timestep ascending
    const int n0 = (gid & 7) * 128;
    const int wm = (wid & 3) * 32;
    const int wn = (wid >> 2) * 64;
    const int ts = gid >> 4;

    // wait for weight split + this timestep's spk conversion
    if (tid == 0) {
        volatile unsigned int* w = &g_wdone;
        while (*w < NPREP_WIN) {}
        volatile unsigned int* p = &g_pdone[ts];
        while (*p == 0u) {}
        __threadfence();
    }
    __syncthreads();

    const uint32_t stA[2]  = {sb,                       sb + STAGE_BYTES};
    const uint32_t stBh[2] = {stA[0] + TILE_BYTES,      stA[1] + TILE_BYTES};
    const uint32_t stBl[2] = {stBh[0] + TILE_BYTES,     stBh[1] + TILE_BYTES};

    float acc[2][8][4];
    #pragma unroll
    for (int mi = 0; mi < 2; mi++)
        #pragma unroll
        for (int nj = 0; nj < 8; nj++)
            #pragma unroll
            for (int q = 0; q < 4; q++) acc[mi][nj][q] = 0.0f;

    copy_tile(stA[0], g_spkb, m0, 0, tid);
    copy_tile(stBh[0], g_WinHi, n0, 0, tid);
    copy_tile(stBl[0], g_WinLo, n0, 0, tid);
    CP_COMMIT();
    copy_tile(stA[1], g_spkb, m0, 64, tid);
    copy_tile(stBh[1], g_WinHi, n0, 64, tid);
    copy_tile(stBl[1], g_WinLo, n0, 64, tid);
    CP_COMMIT();

    const int arow = wm + (lane & 15);
    const int acolL = (lane >> 4) << 4;
    const int brow = (lane & 7) + ((lane >> 4) << 3);
    const int bcolL = ((lane >> 3) & 1) << 4;

    for (int k = 0; k < N_CHUNK; k++) {
        const int s = k & 1;
        if (k < N_CHUNK - 1) CP_WAIT(1); else CP_WAIT(0);
        __syncthreads();

        #pragma unroll
        for (int ks = 0; ks < 4; ks++) {
            const int kb = ks * 32;
            uint32_t af[2][4];
            ldm_x4(af[0], stA[s] + SWZ128((arow)      * 128 + kb + acolL));
            ldm_x4(af[1], stA[s] + SWZ128((arow + 16) * 128 + kb + acolL));

            #pragma unroll
            for (int nb = 0; nb < 4; nb++) {
                const uint32_t boff = SWZ128((wn + nb * 16 + brow) * 128 + kb + bcolL);
                uint32_t bh[4], bl[4];
                ldm_x4(bh, stBh[s] + boff);
                ldm_x4(bl, stBl[s] + boff);
                #pragma unroll
                for (int mi = 0; mi < 2; mi++) {
                    mma_bf16(acc[mi][nb * 2 + 0], af[mi], bh[0], bh[1]);
                    mma_bf16(acc[mi][nb * 2 + 1], af[mi], bh[2], bh[3]);
                    mma_bf16(acc[mi][nb * 2 + 0], af[mi], bl[0], bl[1]);
                    mma_bf16(acc[mi][nb * 2 + 1], af[mi], bl[2], bl[3]);
                }
            }
        }
        __syncthreads();

        if (k + 2 < N_CHUNK) {
            const int k0 = (k + 2) * 64;
            copy_tile(stA[s], g_spkb, m0, k0, tid);
            copy_tile(stBh[s], g_WinHi, n0, k0, tid);
            copy_tile(stBl[s], g_WinLo, n0, k0, tid);
            CP_COMMIT();
        }
    }

    const int r0 = lane >> 2;
    const int c0 = (lane & 3) * 2;
    #pragma unroll
    for (int mi = 0; mi < 2; mi++) {
        #pragma unroll
        for (int nj = 0; nj < 8; nj++) {
            const int row = m0 + wm + mi * 16 + r0;
            const int col = n0 + wn + nj * 8 + c0;
            float* base = &g_Iin[(size_t)row * HID + col];
            *(float2*)base             = make_float2(acc[mi][nj][0], acc[mi][nj][1]);
            *(float2*)(base + 8 * HID) = make_float2(acc[mi][nj][2], acc[mi][nj][3]);
        }
    }

    __syncthreads();
    if (tid == 0) {
        __threadfence();
        atomicAdd(&g_tdone[ts], 1u);
    }
}

// ---------------- loop role (R9-verified, unchanged) ----------------
#define CLUSTER_N   4
#define ROWS_PER_CL 16
#define H_PER_CTA   256

#define L_OFF_POUT  0
#define L_OFF_WPL   32768
#define L_OFF_TH    65536
#define L_OFF_U     73728
#define L_OFF_UPART 75776
#define L_OFF_MBOX  83968
#define LOOP_SMEM   100352

#define FUSED_SMEM  (LOOP_SMEM > GEMM_SMEM ? LOOP_SMEM : GEMM_SMEM)

__device__ void loop_role(char* smraw, int bid,
                          const float* __restrict__ pin, const float* __restrict__ pout,
                          const float* __restrict__ l) {
    const uint32_t sb = smem_u32(smraw);

    cg::cluster_group cl = cg::this_cluster();
    const int rank = cl.block_rank();
    const int cidx = bid / CLUSTER_N;
    const int b0   = cidx * ROWS_PER_CL;
    const int H0   = rank * H_PER_CTA;
    const int tid  = threadIdx.x;
    const int wid  = tid >> 5;
    const int lane = tid & 31;

    for (int i = tid; i < H_PER_CTA * P_DIM; i += 256) {
        int hl = i >> 6;
        int p  = i & 63;
        float pv = pout[(size_t)(H0 + hl) * P_DIM + p];
        *(__nv_bfloat16*)(smraw + L_OFF_POUT + (hl >> 6) * 8192
                          + SWZ128(p * 128 + (hl & 63) * 2)) = __float2bfloat16(pv);
        float wv = pin[(size_t)(H0 + hl) * P_DIM + p] * l[p];
        *(__nv_bfloat16*)(smraw + L_OFF_WPL + SWZ128(hl * 128 + p * 2)) = __float2bfloat16(wv);
    }
    for (int i = tid; i < (8192 + 2048) / 4; i += 256)
        ((uint32_t*)(smraw + L_OFF_TH))[i] = 0;

    const int kg   = wid >> 2;
    const int wn16 = (wid & 3) * 16;
    const int aRow = lane & 15;
    const int aCol = (lane >> 4) << 4;
    const int bRow = (lane & 7) + ((lane >> 4) << 3);
    const int bCol = ((lane >> 3) & 1) << 4;
    const int r    = lane >> 2;
    const int c2   = (lane & 3) * 2;

    const int r_e  = tid >> 4;
    const int pe   = (tid & 15) * 4;
    char* mboxLocal = smraw + L_OFF_MBOX;
    char* peerMb[CLUSTER_N];
    #pragma unroll
    for (int rk = 0; rk < CLUSTER_N; rk++)
        peerMb[rk] = (char*)cl.map_shared_rank((void*)mboxLocal, rk);

    float2 memv[8], rmv[8];
    #pragma unroll
    for (int j = 0; j < 8; j++) { memv[j] = make_float2(0.f, 0.f); rmv[j] = make_float2(-2.f, -2.f); }

    cl.sync();

    for (int t = 0; t < T_STEPS; t++) {
        if (tid == 0) {
            volatile unsigned int* f = &g_tdone[t];
            while (*f < TILES_PER_T) {}
            __threadfence();
        }
        __syncthreads();
        const int buf = t & 1;

        float2 iin[8];
        {
            const size_t base = ((size_t)t * BATCH + b0 + r) * HID + H0 + wid * 32 + c2;
            #pragma unroll
            for (int nb = 0; nb < 2; nb++)
                #pragma unroll
                for (int sub = 0; sub < 2; sub++) {
                    iin[nb * 2 + sub]     = __ldcs((const float2*)&g_Iin[base + nb * 16 + sub * 8]);
                    iin[4 + nb * 2 + sub] = __ldcs((const float2*)&g_Iin[base + 8 * HID + nb * 16 + sub * 8]);
                }
        }

        float accA[2][4] = {{0.f,0.f,0.f,0.f},{0.f,0.f,0.f,0.f}};
        #pragma unroll
        for (int cc = 0; cc < 2; cc++) {
            const int ch = kg * 2 + cc;
            const uint32_t thB = sb + L_OFF_TH + ch * 2048;
            const uint32_t poB = sb + L_OFF_POUT + ch * 8192;
            #pragma unroll
            for (int ks = 0; ks < 4; ks++) {
                const int kb = ks * 32;
                uint32_t af[4], bf[4];
                ldm_x4(af, thB + SWZ128(aRow * 128 + kb + aCol));
                ldm_x4(bf, poB + SWZ128((wn16 + bRow) * 128 + kb + bCol));
                mma_bf16(accA[0], af, bf[0], bf[1]);
                mma_bf16(accA[1], af, bf[2], bf[3]);
            }
        }
        {
            float* up = (float*)(smraw + L_OFF_UPART);
            const int rowA = (kg * 16 + r) * 64 + wn16;
            const int rowB = (kg * 16 + r + 8) * 64 + wn16;
            *(float2*)&up[rowA + 0 + c2] = make_float2(accA[0][0], accA[0][1]);
            *(float2*)&up[rowA + 8 + c2] = make_float2(accA[1][0], accA[1][1]);
            *(float2*)&up[rowB + 0 + c2] = make_float2(accA[0][2], accA[0][3]);
            *(float2*)&up[rowB + 8 + c2] = make_float2(accA[1][2], accA[1][3]);
        }
        __syncthreads();

        {
            const float* up = (const float*)(smraw + L_OFF_UPART);
            float v0 = up[r_e * 64 + pe + 0] + up[(16 + r_e) * 64 + pe + 0];
            float v1 = up[r_e * 64 + pe + 1] + up[(16 + r_e) * 64 + pe + 1];
            float v2 = up[r_e * 64 + pe + 2] + up[(16 + r_e) * 64 + pe + 2];
            float v3 = up[r_e * 64 + pe + 3] + up[(16 + r_e) * 64 + pe + 3];
            uint2 pk;
            __nv_bfloat162 b01 = __floats2bfloat162_rn(v0, v1);
            __nv_bfloat162 b23 = __floats2bfloat162_rn(v2, v3);
            pk.x = *(uint32_t*)&b01;
            pk.y = *(uint32_t*)&b23;
            const int moff = ((buf * CLUSTER_N + rank) * 16 + r_e) * 128 + pe * 2;
            #pragma unroll
            for (int rk = 0; rk < CLUSTER_N; rk++)
                *(uint2*)(peerMb[rk] + moff) = pk;
        }
        cl.sync();

        {
            float s0 = 0.f, s1 = 0.f, s2 = 0.f, s3 = 0.f;
            #pragma unroll
            for (int rk = 0; rk < CLUSTER_N; rk++) {
                uint2 q = *(uint2*)(mboxLocal + ((buf * CLUSTER_N + rk) * 16 + r_e) * 128 + pe * 2);
                float2 f01 = __bfloat1622float2(*(__nv_bfloat162*)&q.x);
                float2 f23 = __bfloat1622float2(*(__nv_bfloat162*)&q.y);
                s0 += f01.x; s1 += f01.y; s2 += f23.x; s3 += f23.y;
            }
            uint2 pk;
            __nv_bfloat162 b01 = __floats2bfloat162_rn(s0, s1);
            __nv_bfloat162 b23 = __floats2bfloat162_rn(s2, s3);
            pk.x = *(uint32_t*)&b01;
            pk.y = *(uint32_t*)&b23;
            *(uint2*)(smraw + L_OFF_U + SWZ128(r_e * 128 + pe * 2)) = pk;
        }
        __syncthreads();

        float accB[2][2][4];
        #pragma unroll
        for (int nb = 0; nb < 2; nb++)
            #pragma unroll
            for (int sub = 0; sub < 2; sub++)
                #pragma unroll
                for (int q = 0; q < 4; q++) accB[nb][sub][q] = 0.f;

        const uint32_t uB = sb + L_OFF_U;
        const uint32_t wB = sb + L_OFF_WPL;
        #pragma unroll
        for (int ks = 0; ks < 4; ks++) {
            const int kb = ks * 32;
            uint32_t af[4];
            ldm_x4(af, uB + SWZ128(aRow * 128 + kb + aCol));
            #pragma unroll
            for (int nb = 0; nb < 2; nb++) {
                uint32_t bf[4];
                ldm_x4(bf, wB + SWZ128((wid * 32 + nb * 16 + bRow) * 128 + kb + bCol));
                mma_bf16(accB[nb][0], af, bf[0], bf[1]);
                mma_bf16(accB[nb][1], af, bf[2], bf[3]);
            }
        }

        #pragma unroll
        for (int nb = 0; nb < 2; nb++) {
            #pragma unroll
            for (int sub = 0; sub < 2; sub++) {
                const int j  = nb * 2 + sub;
                const int hc = wid * 32 + nb * 16 + sub * 8 + c2;
                const uint32_t thBase = (uint32_t)(L_OFF_TH + (hc >> 6) * 2048);
                {
                    float m0 = (iin[j].x + accB[nb][sub][0] - memv[j].x) * ALPHA;
                    float m1 = (iin[j].y + accB[nb][sub][1] - memv[j].y) * ALPHA;
                    memv[j].x = m0;  memv[j].y = m1;
                    float tv0 = tanhf(m0), tv1 = tanhf(m1);
                    rmv[j].x = fmaxf(rmv[j].x, tv0);
                    rmv[j].y = fmaxf(rmv[j].y, tv1);
                    *(__nv_bfloat162*)(smraw + thBase + SWZ128(r * 128 + (hc & 63) * 2)) =
                        __floats2bfloat162_rn(tv0, tv1);
                }
                {
                    float m0 = (iin[4 + j].x + accB[nb][sub][2] - memv[4 + j].x) * ALPHA;
                    float m1 = (iin[4 + j].y + accB[nb][sub][3] - memv[4 + j].y) * ALPHA;
                    memv[4 + j].x = m0;  memv[4 + j].y = m1;
                    float tv0 = tanhf(m0), tv1 = tanhf(m1);
                    rmv[4 + j].x = fmaxf(rmv[4 + j].x, tv0);
                    rmv[4 + j].y = fmaxf(rmv[4 + j].y, tv1);
                    *(__nv_bfloat162*)(smraw + thBase + SWZ128((r + 8) * 128 + (hc & 63) * 2)) =
                        __floats2bfloat162_rn(tv0, tv1);
                }
            }
        }
    }

    #pragma unroll
    for (int nb = 0; nb < 2; nb++)
        #pragma unroll
        for (int sub = 0; sub < 2; sub++) {
            const int j  = nb * 2 + sub;
            const int hc = wid * 32 + nb * 16 + sub * 8 + c2;
            *(float2*)&g_rm[(size_t)(b0 + r) * HID + H0 + hc]     = rmv[j];
            *(float2*)&g_rm[(size_t)(b0 + 8 + r) * HID + H0 + hc] = rmv[4 + j];
        }
}

// ---------------- fused heterogeneous kernel ----------------
__global__ void __cluster_dims__(CLUSTER_N, 1, 1) __launch_bounds__(256, 2)
fused_kernel(const float* __restrict__ spk, const float* __restrict__ Win,
             const float* __restrict__ pin, const float* __restrict__ pout,
             const float* __restrict__ l) {
    extern __shared__ char smraw[];
    const int bid = blockIdx.x;
    if (bid < NCTAS_LOOP) {
        loop_role(smraw, bid, pin, pout, l);
    } else if (bid < BID_WIN0) {
        prep_spk_role(spk, bid - BID_PREP0);
    } else if (bid < BID_GEMM0) {
        prep_win_role(Win, bid - BID_WIN0);
    } else {
        gemm_role(smraw, bid - BID_GEMM0);
    }
}

// ---------------- readout ----------------
__global__ __launch_bounds__(128) void readout_kernel(const float* __restrict__ Wout,
                                                      float* __restrict__ out) {
    const int b    = blockIdx.x;
    const int tid  = threadIdx.x;
    const int lane = tid & 31;
    const int wid  = tid >> 5;
    __shared__ float red[4][OUTD];

    float pacc[OUTD];
    #pragma unroll
    for (int o = 0; o < OUTD; o++) pacc[o] = 0.0f;

    #pragma unroll
    for (int hh = 0; hh < HID / 128; hh++) {
        int h = tid + hh * 128;
        float rv = g_rm[(size_t)b * HID + h];
        #pragma unroll
        for (int o = 0; o < OUTD; o++) pacc[o] = fmaf(rv, Wout[o * HID + h], pacc[o]);
    }
    #pragma unroll
    for (int o = 0; o < OUTD; o++) {
        #pragma unroll
        for (int off = 16; off > 0; off >>= 1)
            pacc[o] += __shfl_down_sync(0xffffffffu, pacc[o], off);
    }
    if (lane == 0) {
        #pragma unroll
        for (int o = 0; o < OUTD; o++) red[wid][o] = pacc[o];
    }
    __syncthreads();
    if (tid == 0) {
        float v[OUTD];
        #pragma unroll
        for (int o = 0; o < OUTD; o++)
            v[o] = red[0][o] + red[1][o] + red[2][o] + red[3][o];
        float mx = v[0];
        #pragma unroll
        for (int o = 1; o < OUTD; o++) mx = fmaxf(mx, v[o]);
        float e[OUTD], sum = 0.0f;
        #pragma unroll
        for (int o = 0; o < OUTD; o++) { e[o] = expf(v[o] - mx); sum += e[o]; }
        float inv = 1.0f / sum;
        #pragma unroll
        for (int o = 0; o < OUTD; o++) out[b * OUTD + o] = e[o] * inv;
    }
}

// ---------------- launch ----------------
extern "C" void kernel_launch(void* const* d_in, const int* in_sizes, int n_in,
                              void* d_out, int out_size) {
    const float* spk  = (const float*)d_in[0];
    const float* Win  = (const float*)d_in[1];
    const float* Wout = (const float*)d_in[2];
    const float* pin  = (const float*)d_in[3];
    const float* pout = (const float*)d_in[4];
    const float* l    = (const float*)d_in[5];
    float* out = (float*)d_out;

    static bool init = false;
    if (!init) {
        cudaFuncSetAttribute(fused_kernel, cudaFuncAttributeMaxDynamicSharedMemorySize, FUSED_SMEM);
        init = true;
    }

    zero_flags_kernel<<<1, 128>>>();
    fused_kernel<<<NCTAS_ALL, 256, FUSED_SMEM>>>(spk, Win, pin, pout, l);
    readout_kernel<<<BATCH, 128>>>(Wout, out);
}

// round 12
// speedup vs baseline: 2.2236x; 1.1050x over previous
#include <cuda_runtime.h>
#include <cuda_bf16.h>
#include <cuda_fp16.h>
#include <cooperative_groups.h>
#include <math.h>
#include <stdint.h>

namespace cg = cooperative_groups;

#define T_STEPS 100
#define BATCH   256
#define IN_DIM  784
#define HID     1024
#define OUTD    10
#define P_DIM   64
#define ALPHA   0.05f   // DT / TAUM

#define M_TOT   (T_STEPS * BATCH)   // 25600
#define K_PAD   832                 // 13 * 64 fp16 (128B rows)
#define N_CHUNK 13
#define TILES_PER_T 16

#define NCTAS_LOOP 64               // 16 clusters x 4 (16 batch rows each)
#define NCTAS_GEMM 1600
#define NCTAS_ALL  (NCTAS_LOOP + NCTAS_GEMM)

// ---------------- scratch (static device globals) ----------------
__device__ float  g_Iin[(size_t)T_STEPS * BATCH * HID];
__device__ float  g_rm [BATCH * HID];
__device__ __half g_spkh[(size_t)M_TOT * K_PAD];   // fp16 spikes (exact)
__device__ __half g_WinH[(size_t)HID * K_PAD];     // fp16 Win
__device__ unsigned int g_tdone[T_STEPS];

// ---------------- helpers ----------------
__device__ __forceinline__ uint32_t smem_u32(const void* p) {
    uint32_t a;
    asm("{ .reg .u64 t; cvta.to.shared.u64 t, %1; cvt.u32.u64 %0, t; }" : "=r"(a) : "l"(p));
    return a;
}
#define SWZ128(o) ((o) ^ (((o) >> 3) & 0x70))
#define CP_COMMIT() asm volatile("cp.async.commit_group;" ::: "memory")
#define CP_WAIT(n)  asm volatile("cp.async.wait_group %0;" :: "n"(n) : "memory")

__device__ __forceinline__ void ldm_x4(uint32_t* r, uint32_t addr) {
    asm volatile("ldmatrix.sync.aligned.m8n8.x4.shared.b16 {%0,%1,%2,%3}, [%4];"
                 : "=r"(r[0]), "=r"(r[1]), "=r"(r[2]), "=r"(r[3]) : "r"(addr));
}
__device__ __forceinline__ void mma_bf16(float* c, const uint32_t* a, uint32_t b0, uint32_t b1) {
    asm volatile("mma.sync.aligned.m16n8k16.row.col.f32.bf16.bf16.f32 "
                 "{%0,%1,%2,%3}, {%4,%5,%6,%7}, {%8,%9}, {%0,%1,%2,%3};"
                 : "+f"(c[0]), "+f"(c[1]), "+f"(c[2]), "+f"(c[3])
                 : "r"(a[0]), "r"(a[1]), "r"(a[2]), "r"(a[3]), "r"(b0), "r"(b1));
}
__device__ __forceinline__ void mma_f16(float* c, const uint32_t* a, uint32_t b0, uint32_t b1) {
    asm volatile("mma.sync.aligned.m16n8k16.row.col.f32.f16.f16.f32 "
                 "{%0,%1,%2,%3}, {%4,%5,%6,%7}, {%8,%9}, {%0,%1,%2,%3};"
                 : "+f"(c[0]), "+f"(c[1]), "+f"(c[2]), "+f"(c[3])
                 : "r"(a[0]), "r"(a[1]), "r"(a[2]), "r"(a[3]), "r"(b0), "r"(b1));
}

// ---------------- prep kernels ----------------
__global__ void prep_spk_kernel(const float* __restrict__ spk) {
    int i = blockIdx.x * blockDim.x + threadIdx.x;
    if (i >= M_TOT * (K_PAD / 8)) return;
    int row = i / (K_PAD / 8);
    int c0  = (i % (K_PAD / 8)) * 8;
    __half v[8];
    if (c0 < IN_DIM) {   // 784 = 98*8: full float4 pair valid whenever c0 < 784
        const float4* src = (const float4*)&spk[(size_t)row * IN_DIM + c0];
        float4 f0 = src[0], f1 = src[1];
        v[0] = __float2half_rn(f0.x); v[1] = __float2half_rn(f0.y);
        v[2] = __float2half_rn(f0.z); v[3] = __float2half_rn(f0.w);
        v[4] = __float2half_rn(f1.x); v[5] = __float2half_rn(f1.y);
        v[6] = __float2half_rn(f1.z); v[7] = __float2half_rn(f1.w);
    } else {
        #pragma unroll
        for (int j = 0; j < 8; j++) v[j] = __float2half_rn(0.0f);
    }
    *(uint4*)&g_spkh[(size_t)row * K_PAD + c0] = *(uint4*)v;
}

__global__ void prep_win_kernel(const float* __restrict__ Win) {
    int i = blockIdx.x * blockDim.x + threadIdx.x;
    if (blockIdx.x == 0 && threadIdx.x < T_STEPS) g_tdone[threadIdx.x] = 0u;
    if (i >= HID * (K_PAD / 8)) return;
    int row = i / (K_PAD / 8);
    int c0  = (i % (K_PAD / 8)) * 8;
    __half v[8];
    if (c0 < IN_DIM) {
        const float4* src = (const float4*)&Win[(size_t)row * IN_DIM + c0];
        float4 f0 = src[0], f1 = src[1];
        v[0] = __float2half_rn(f0.x); v[1] = __float2half_rn(f0.y);
        v[2] = __float2half_rn(f0.z); v[3] = __float2half_rn(f0.w);
        v[4] = __float2half_rn(f1.x); v[5] = __float2half_rn(f1.y);
        v[6] = __float2half_rn(f1.z); v[7] = __float2half_rn(f1.w);
    } else {
        #pragma unroll
        for (int j = 0; j < 8; j++) v[j] = __float2half_rn(0.0f);
    }
    *(uint4*)&g_WinH[(size_t)row * K_PAD + c0] = *(uint4*)v;
}

// ---------------- gemm role: Iin = spkh @ WinH^T (single fp16 GEMM) ----------------
#define TILE_BYTES  16384                       // 128 rows * 128 B
#define STAGE_BYTES (2 * TILE_BYTES)            // A + B
#define GEMM_SMEM   (2 * STAGE_BYTES)           // 65536

__device__ __forceinline__ void copy_tile(uint32_t sdst, const __half* __restrict__ g,
                                          int row0, int k0, int tid) {
    #pragma unroll
    for (int j = 0; j < 4; j++) {
        int i   = tid + j * 256;
        int row = i >> 3;
        int cb  = i & 7;
        const void* gp = g + (size_t)(row0 + row) * K_PAD + k0 + cb * 8;
        uint32_t so = sdst + SWZ128(row * 128 + cb * 16);
        asm volatile("cp.async.cg.shared.global [%0], [%1], 16;" :: "r"(so), "l"(gp));
    }
}

__device__ void gemm_role(char* smraw, int gid) {
    const uint32_t sb  = smem_u32(smraw);
    const int tid  = threadIdx.x;
    const int wid  = tid >> 5;
    const int lane = tid & 31;
    const int m0 = (gid >> 3) * 128;     // m-tile ascending == timestep ascending
    const int n0 = (gid & 7) * 128;
    const int wm = (wid & 3) * 32;
    const int wn = (wid >> 2) * 64;

    const uint32_t stA[2] = {sb,                  sb + STAGE_BYTES};
    const uint32_t stB[2] = {stA[0] + TILE_BYTES, stA[1] + TILE_BYTES};

    float acc[2][8][4];
    #pragma unroll
    for (int mi = 0; mi < 2; mi++)
        #pragma unroll
        for (int nj = 0; nj < 8; nj++)
            #pragma unroll
            for (int q = 0; q < 4; q++) acc[mi][nj][q] = 0.0f;

    copy_tile(stA[0], g_spkh, m0, 0, tid);
    copy_tile(stB[0], g_WinH, n0, 0, tid);
    CP_COMMIT();
    copy_tile(stA[1], g_spkh, m0, 64, tid);
    copy_tile(stB[1], g_WinH, n0, 64, tid);
    CP_COMMIT();

    const int arow = wm + (lane & 15);
    const int acolL = (lane >> 4) << 4;
    const int brow = (lane & 7) + ((lane >> 4) << 3);
    const int bcolL = ((lane >> 3) & 1) << 4;

    for (int k = 0; k < N_CHUNK; k++) {
        const int s = k & 1;
        if (k < N_CHUNK - 1) CP_WAIT(1); else CP_WAIT(0);
        __syncthreads();

        #pragma unroll
        for (int ks = 0; ks < 4; ks++) {
            const int kb = ks * 32;
            uint32_t af[2][4];
            ldm_x4(af[0], stA[s] + SWZ128((arow)      * 128 + kb + acolL));
            ldm_x4(af[1], stA[s] + SWZ128((arow + 16) * 128 + kb + acolL));

            #pragma unroll
            for (int nb = 0; nb < 4; nb++) {
                const uint32_t boff = SWZ128((wn + nb * 16 + brow) * 128 + kb + bcolL);
                uint32_t bh[4];
                ldm_x4(bh, stB[s] + boff);
                #pragma unroll
                for (int mi = 0; mi < 2; mi++) {
                    mma_f16(acc[mi][nb * 2 + 0], af[mi], bh[0], bh[1]);
                    mma_f16(acc[mi][nb * 2 + 1], af[mi], bh[2], bh[3]);
                }
            }
        }
        __syncthreads();

        if (k + 2 < N_CHUNK) {
            const int k0 = (k + 2) * 64;
            copy_tile(stA[s], g_spkh, m0, k0, tid);
            copy_tile(stB[s], g_WinH, n0, k0, tid);
            CP_COMMIT();
        }
    }

    const int r0 = lane >> 2;
    const int c0 = (lane & 3) * 2;
    #pragma unroll
    for (int mi = 0; mi < 2; mi++) {
        #pragma unroll
        for (int nj = 0; nj < 8; nj++) {
            const int row = m0 + wm + mi * 16 + r0;
            const int col = n0 + wn + nj * 8 + c0;
            float* base = &g_Iin[(size_t)row * HID + col];
            *(float2*)base             = make_float2(acc[mi][nj][0], acc[mi][nj][1]);
            *(float2*)(base + 8 * HID) = make_float2(acc[mi][nj][2], acc[mi][nj][3]);
        }
    }

    __syncthreads();
    if (tid == 0) {
        __threadfence();
        atomicAdd(&g_tdone[gid >> 4], 1u);
    }
}

// ---------------- loop role (R9-verified, unchanged) ----------------
#define CLUSTER_N   4
#define ROWS_PER_CL 16
#define H_PER_CTA   256

#define L_OFF_POUT  0
#define L_OFF_WPL   32768
#define L_OFF_TH    65536
#define L_OFF_U     73728
#define L_OFF_UPART 75776
#define L_OFF_MBOX  83968
#define LOOP_SMEM   100352

#define FUSED_SMEM  (LOOP_SMEM > GEMM_SMEM ? LOOP_SMEM : GEMM_SMEM)

__device__ void loop_role(char* smraw, int bid,
                          const float* __restrict__ pin, const float* __restrict__ pout,
                          const float* __restrict__ l) {
    const uint32_t sb = smem_u32(smraw);

    cg::cluster_group cl = cg::this_cluster();
    const int rank = cl.block_rank();
    const int cidx = bid / CLUSTER_N;
    const int b0   = cidx * ROWS_PER_CL;
    const int H0   = rank * H_PER_CTA;
    const int tid  = threadIdx.x;
    const int wid  = tid >> 5;
    const int lane = tid & 31;

    for (int i = tid; i < H_PER_CTA * P_DIM; i += 256) {
        int hl = i >> 6;
        int p  = i & 63;
        float pv = pout[(size_t)(H0 + hl) * P_DIM + p];
        *(__nv_bfloat16*)(smraw + L_OFF_POUT + (hl >> 6) * 8192
                          + SWZ128(p * 128 + (hl & 63) * 2)) = __float2bfloat16(pv);
        float wv = pin[(size_t)(H0 + hl) * P_DIM + p] * l[p];
        *(__nv_bfloat16*)(smraw + L_OFF_WPL + SWZ128(hl * 128 + p * 2)) = __float2bfloat16(wv);
    }
    for (int i = tid; i < (8192 + 2048) / 4; i += 256)
        ((uint32_t*)(smraw + L_OFF_TH))[i] = 0;

    const int kg   = wid >> 2;
    const int wn16 = (wid & 3) * 16;
    const int aRow = lane & 15;
    const int aCol = (lane >> 4) << 4;
    const int bRow = (lane & 7) + ((lane >> 4) << 3);
    const int bCol = ((lane >> 3) & 1) << 4;
    const int r    = lane >> 2;
    const int c2   = (lane & 3) * 2;

    const int r_e  = tid >> 4;
    const int pe   = (tid & 15) * 4;
    char* mboxLocal = smraw + L_OFF_MBOX;
    char* peerMb[CLUSTER_N];
    #pragma unroll
    for (int rk = 0; rk < CLUSTER_N; rk++)
        peerMb[rk] = (char*)cl.map_shared_rank((void*)mboxLocal, rk);

    float2 memv[8], rmv[8];
    #pragma unroll
    for (int j = 0; j < 8; j++) { memv[j] = make_float2(0.f, 0.f); rmv[j] = make_float2(-2.f, -2.f); }

    cl.sync();

    for (int t = 0; t < T_STEPS; t++) {
        if (tid == 0) {
            volatile unsigned int* f = &g_tdone[t];
            while (*f < TILES_PER_T) {}
            __threadfence();
        }
        __syncthreads();
        const int buf = t & 1;

        float2 iin[8];
        {
            const size_t base = ((size_t)t * BATCH + b0 + r) * HID + H0 + wid * 32 + c2;
            #pragma unroll
            for (int nb = 0; nb < 2; nb++)
                #pragma unroll
                for (int sub = 0; sub < 2; sub++) {
                    iin[nb * 2 + sub]     = __ldcs((const float2*)&g_Iin[base + nb * 16 + sub * 8]);
                    iin[4 + nb * 2 + sub] = __ldcs((const float2*)&g_Iin[base + 8 * HID + nb * 16 + sub * 8]);
                }
        }

        float accA[2][4] = {{0.f,0.f,0.f,0.f},{0.f,0.f,0.f,0.f}};
        #pragma unroll
        for (int cc = 0; cc < 2; cc++) {
            const int ch = kg * 2 + cc;
            const uint32_t thB = sb + L_OFF_TH + ch * 2048;
            const uint32_t poB = sb + L_OFF_POUT + ch * 8192;
            #pragma unroll
            for (int ks = 0; ks < 4; ks++) {
                const int kb = ks * 32;
                uint32_t af[4], bf[4];
                ldm_x4(af, thB + SWZ128(aRow * 128 + kb + aCol));
                ldm_x4(bf, poB + SWZ128((wn16 + bRow) * 128 + kb + bCol));
                mma_bf16(accA[0], af, bf[0], bf[1]);
                mma_bf16(accA[1], af, bf[2], bf[3]);
            }
        }
        {
            float* up = (float*)(smraw + L_OFF_UPART);
            const int rowA = (kg * 16 + r) * 64 + wn16;
            const int rowB = (kg * 16 + r + 8) * 64 + wn16;
            *(float2*)&up[rowA + 0 + c2] = make_float2(accA[0][0], accA[0][1]);
            *(float2*)&up[rowA + 8 + c2] = make_float2(accA[1][0], accA[1][1]);
            *(float2*)&up[rowB + 0 + c2] = make_float2(accA[0][2], accA[0][3]);
            *(float2*)&up[rowB + 8 + c2] = make_float2(accA[1][2], accA[1][3]);
        }
        __syncthreads();

        {
            const float* up = (const float*)(smraw + L_OFF_UPART);
            float v0 = up[r_e * 64 + pe + 0] + up[(16 + r_e) * 64 + pe + 0];
            float v1 = up[r_e * 64 + pe + 1] + up[(16 + r_e) * 64 + pe + 1];
            float v2 = up[r_e * 64 + pe + 2] + up[(16 + r_e) * 64 + pe + 2];
            float v3 = up[r_e * 64 + pe + 3] + up[(16 + r_e) * 64 + pe + 3];
            uint2 pk;
            __nv_bfloat162 b01 = __floats2bfloat162_rn(v0, v1);
            __nv_bfloat162 b23 = __floats2bfloat162_rn(v2, v3);
            pk.x = *(uint32_t*)&b01;
            pk.y = *(uint32_t*)&b23;
            const int moff = ((buf * CLUSTER_N + rank) * 16 + r_e) * 128 + pe * 2;
            #pragma unroll
            for (int rk = 0; rk < CLUSTER_N; rk++)
                *(uint2*)(peerMb[rk] + moff) = pk;
        }
        cl.sync();

        {
            float s0 = 0.f, s1 = 0.f, s2 = 0.f, s3 = 0.f;
            #pragma unroll
            for (int rk = 0; rk < CLUSTER_N; rk++) {
                uint2 q = *(uint2*)(mboxLocal + ((buf * CLUSTER_N + rk) * 16 + r_e) * 128 + pe * 2);
                float2 f01 = __bfloat1622float2(*(__nv_bfloat162*)&q.x);
                float2 f23 = __bfloat1622float2(*(__nv_bfloat162*)&q.y);
                s0 += f01.x; s1 += f01.y; s2 += f23.x; s3 += f23.y;
            }
            uint2 pk;
            __nv_bfloat162 b01 = __floats2bfloat162_rn(s0, s1);
            __nv_bfloat162 b23 = __floats2bfloat162_rn(s2, s3);
            pk.x = *(uint32_t*)&b01;
            pk.y = *(uint32_t*)&b23;
            *(uint2*)(smraw + L_OFF_U + SWZ128(r_e * 128 + pe * 2)) = pk;
        }
        __syncthreads();

        float accB[2][2][4];
        #pragma unroll
        for (int nb = 0; nb < 2; nb++)
            #pragma unroll
            for (int sub = 0; sub < 2; sub++)
                #pragma unroll
                for (int q = 0; q < 4; q++) accB[nb][sub][q] = 0.f;

        const uint32_t uB = sb + L_OFF_U;
        const uint32_t wB = sb + L_OFF_WPL;
        #pragma unroll
        for (int ks = 0; ks < 4; ks++) {
            const int kb = ks * 32;
            uint32_t af[4];
            ldm_x4(af, uB + SWZ128(aRow * 128 + kb + aCol));
            #pragma unroll
            for (int nb = 0; nb < 2; nb++) {
                uint32_t bf[4];
                ldm_x4(bf, wB + SWZ128((wid * 32 + nb * 16 + bRow) * 128 + kb + bCol));
                mma_bf16(accB[nb][0], af, bf[0], bf[1]);
                mma_bf16(accB[nb][1], af, bf[2], bf[3]);
            }
        }

        #pragma unroll
        for (int nb = 0; nb < 2; nb++) {
            #pragma unroll
            for (int sub = 0; sub < 2; sub++) {
                const int j  = nb * 2 + sub;
                const int hc = wid * 32 + nb * 16 + sub * 8 + c2;
                const uint32_t thBase = (uint32_t)(L_OFF_TH + (hc >> 6) * 2048);
                {
                    float m0 = (iin[j].x + accB[nb][sub][0] - memv[j].x) * ALPHA;
                    float m1 = (iin[j].y + accB[nb][sub][1] - memv[j].y) * ALPHA;
                    memv[j].x = m0;  memv[j].y = m1;
                    float tv0 = tanhf(m0), tv1 = tanhf(m1);
                    rmv[j].x = fmaxf(rmv[j].x, tv0);
                    rmv[j].y = fmaxf(rmv[j].y, tv1);
                    *(__nv_bfloat162*)(smraw + thBase + SWZ128(r * 128 + (hc & 63) * 2)) =
                        __floats2bfloat162_rn(tv0, tv1);
                }
                {
                    float m0 = (iin[4 + j].x + accB[nb][sub][2] - memv[4 + j].x) * ALPHA;
                    float m1 = (iin[4 + j].y + accB[nb][sub][3] - memv[4 + j].y) * ALPHA;
                    memv[4 + j].x = m0;  memv[4 + j].y = m1;
                    float tv0 = tanhf(m0), tv1 = tanhf(m1);
                    rmv[4 + j].x = fmaxf(rmv[4 + j].x, tv0);
                    rmv[4 + j].y = fmaxf(rmv[4 + j].y, tv1);
                    *(__nv_bfloat162*)(smraw + thBase + SWZ128((r + 8) * 128 + (hc & 63) * 2)) =
                        __floats2bfloat162_rn(tv0, tv1);
                }
            }
        }
    }

    #pragma unroll
    for (int nb = 0; nb < 2; nb++)
        #pragma unroll
        for (int sub = 0; sub < 2; sub++) {
            const int j  = nb * 2 + sub;
            const int hc = wid * 32 + nb * 16 + sub * 8 + c2;
            *(float2*)&g_rm[(size_t)(b0 + r) * HID + H0 + hc]     = rmv[j];
            *(float2*)&g_rm[(size_t)(b0 + 8 + r) * HID + H0 + hc] = rmv[4 + j];
        }
}

// ---------------- fused heterogeneous kernel ----------------
__global__ void __cluster_dims__(CLUSTER_N, 1, 1) __launch_bounds__(256, 2)
fused_kernel(const float* __restrict__ pin, const float* __restrict__ pout,
             const float* __restrict__ l) {
    extern __shared__ char smraw[];
    const int bid = blockIdx.x;
    if (bid < NCTAS_LOOP) {
        loop_role(smraw, bid, pin, pout, l);
    } else {
        gemm_role(smraw, bid - NCTAS_LOOP);
    }
}

// ---------------- readout ----------------
__global__ __launch_bounds__(128) void readout_kernel(const float* __restrict__ Wout,
                                                      float* __restrict__ out) {
    const int b    = blockIdx.x;
    const int tid  = threadIdx.x;
    const int lane = tid & 31;
    const int wid  = tid >> 5;
    __shared__ float red[4][OUTD];

    float pacc[OUTD];
    #pragma unroll
    for (int o = 0; o < OUTD; o++) pacc[o] = 0.0f;

    #pragma unroll
    for (int hh = 0; hh < HID / 128; hh++) {
        int h = tid + hh * 128;
        float rv = g_rm[(size_t)b * HID + h];
        #pragma unroll
        for (int o = 0; o < OUTD; o++) pacc[o] = fmaf(rv, Wout[o * HID + h], pacc[o]);
    }
    #pragma unroll
    for (int o = 0; o < OUTD; o++) {
        #pragma unroll
        for (int off = 16; off > 0; off >>= 1)
            pacc[o] += __shfl_down_sync(0xffffffffu, pacc[o], off);
    }
    if (lane == 0) {
        #pragma unroll
        for (int o = 0; o < OUTD; o++) red[wid][o] = pacc[o];
    }
    __syncthreads();
    if (tid == 0) {
        float v[OUTD];
        #pragma unroll
        for (int o = 0; o < OUTD; o++)
            v[o] = red[0][o] + red[1][o] + red[2][o] + red[3][o];
        float mx = v[0];
        #pragma unroll
        for (int o = 1; o < OUTD; o++) mx = fmaxf(mx, v[o]);
        float e[OUTD], sum = 0.0f;
        #pragma unroll
        for (int o = 0; o < OUTD; o++) { e[o] = expf(v[o] - mx); sum += e[o]; }
        float inv = 1.0f / sum;
        #pragma unroll
        for (int o = 0; o < OUTD; o++) out[b * OUTD + o] = e[o] * inv;
    }
}

// ---------------- launch ----------------
extern "C" void kernel_launch(void* const* d_in, const int* in_sizes, int n_in,
                              void* d_out, int out_size) {
    const float* spk  = (const float*)d_in[0];
    const float* Win  = (const float*)d_in[1];
    const float* Wout = (const float*)d_in[2];
    const float* pin  = (const float*)d_in[3];
    const float* pout = (const float*)d_in[4];
    const float* l    = (const float*)d_in[5];
    float* out = (float*)d_out;

    static bool init = false;
    if (!init) {
        cudaFuncSetAttribute(fused_kernel, cudaFuncAttributeMaxDynamicSharedMemorySize, FUSED_SMEM);
        init = true;
    }

    {
        int n = M_TOT * (K_PAD / 8);
        prep_spk_kernel<<<(n + 255) / 256, 256>>>(spk);
    }
    {
        int n = HID * (K_PAD / 8);
        prep_win_kernel<<<(n + 255) / 256, 256>>>(Win);
    }
    fused_kernel<<<NCTAS_ALL, 256, FUSED_SMEM>>>(pin, pout, l);
    readout_kernel<<<BATCH, 128>>>(Wout, out);
}